// round 1
// baseline (speedup 1.0000x reference)
#include <cuda_runtime.h>
#include <cuda_bf16.h>
#include <math.h>

// ---------------- scratch (no allocations allowed) ----------------
__device__ float g_Wp[512 * 256];    // mean-over-heads of value_w: (HID=512, VSZ=256)
__device__ float g_M[128 * 256];     // pre_fc_w @ Wp: (OBS=128, VSZ=256)
__device__ float g_d[256];           // pre_fc_b @ Wp
__device__ float g_c8[256];          // mean-over-heads value_b / 8
__device__ float g_alpha[16];        // per-option: sum_{top8} sigmoid(score) / 64

// ---------------- kernel 1: per-option LUT + c/8 ----------------
__global__ void prep_kernel(const float* __restrict__ pw,   // (16,64)
                            const float* __restrict__ pb,   // (64,)
                            const float* __restrict__ vb) { // (1024,)
    __shared__ float s[16][64];
    int t = threadIdx.x;  // 256 threads
    for (int i = t; i < 16 * 64; i += 256) {
        int o = i >> 6, n = i & 63;
        s[o][n] = pw[o * 64 + n] + pb[n];
    }
    // c/8 for all 256 output columns
    float c = 0.25f * (vb[t] + vb[t + 256] + vb[t + 512] + vb[t + 768]);
    g_c8[t] = 0.125f * c;
    __syncthreads();
    if (t < 16) {
        float S = 0.f;
        for (int j = 0; j < 8; j++) {
            float bv = -1e30f; int bi = 0;
            for (int n = 0; n < 64; n++) {
                float val = s[t][n];
                if (val > bv) { bv = val; bi = n; }
            }
            S += 1.f / (1.f + expf(-bv));   // softmax([x,0])[0] = sigmoid(x)
            s[t][bi] = -1e30f;
        }
        g_alpha[t] = S * (1.0f / 64.0f);
    }
}

// ---------------- kernel 2: Wp = mean_h value_w[:, h*256+v]; zero M,d ----------------
__global__ void wprime_kernel(const float* __restrict__ vw) { // (512,1024)
    int k = blockIdx.x;      // 0..511
    int v = threadIdx.x;     // 0..255
    const float* r = vw + (size_t)k * 1024;
    g_Wp[k * 256 + v] = 0.25f * (r[v] + r[v + 256] + r[v + 512] + r[v + 768]);
    if (k < 128) g_M[k * 256 + v] = 0.f;
    if (k == 128) g_d[v] = 0.f;
}

// ---------------- kernel 3: M = pre_fc_w @ Wp ; d = pre_fc_b @ Wp (split-K=4) ----------------
// grid (33, 4): 33 row-tiles of 4 rows covering 129 "rows" (128 A rows + bias row), 4 K-splits of 128.
__global__ __launch_bounds__(256) void mgemm_kernel(const float* __restrict__ A,     // (128,512)
                                                    const float* __restrict__ bias) { // (512,)
    __shared__ float sA[4][128];
    int r0 = blockIdx.x * 4;
    int kk = blockIdx.y * 128;
    int tid = threadIdx.x;     // 256, indexes v
    for (int i = tid; i < 4 * 128; i += 256) {
        int rr = i >> 7, k = i & 127;
        int row = r0 + rr;
        sA[rr][k] = (row < 128) ? A[row * 512 + kk + k]
                  : (row == 128 ? bias[kk + k] : 0.f);
    }
    __syncthreads();
    float acc0 = 0.f, acc1 = 0.f, acc2 = 0.f, acc3 = 0.f;
    #pragma unroll 8
    for (int k = 0; k < 128; k++) {
        float wp = g_Wp[(kk + k) * 256 + tid];
        acc0 += sA[0][k] * wp;
        acc1 += sA[1][k] * wp;
        acc2 += sA[2][k] * wp;
        acc3 += sA[3][k] * wp;
    }
    float acc[4] = {acc0, acc1, acc2, acc3};
    #pragma unroll
    for (int r = 0; r < 4; r++) {
        int row = r0 + r;
        if (row < 128)       atomicAdd(&g_M[row * 256 + tid], acc[r]);
        else if (row == 128) atomicAdd(&g_d[tid], acc[r]);
    }
}

// ---------------- kernel 4: out = alpha[opt[b]] * (x @ M + d) + c/8 ----------------
// 8192x256, K=128. Block tile 128x128, 256 threads, 8x8 per thread. grid (64, 2).
__global__ __launch_bounds__(256) void main_gemm(const float* __restrict__ x,    // (8192,128)
                                                 const int* __restrict__ opt,    // (8192,)
                                                 float* __restrict__ out) {      // (8192,256)
    __shared__ float xs[16][128];  // [k][m]
    __shared__ float ms[16][128];  // [k][n]
    int m0 = blockIdx.x * 128;
    int n0 = blockIdx.y * 128;
    int tid = threadIdx.x;
    int tx = tid & 15;       // n-dir
    int ty = tid >> 4;       // m-dir
    float acc[8][8];
    #pragma unroll
    for (int i = 0; i < 8; i++)
        #pragma unroll
        for (int j = 0; j < 8; j++) acc[i][j] = 0.f;

    for (int kk = 0; kk < 128; kk += 16) {
        // x tile: 128 rows x 16 k -> xs[k][m] (transpose on store)
        #pragma unroll
        for (int i = 0; i < 2; i++) {
            int fid = tid + i * 256;          // 0..511 float4s
            int row = fid >> 2;               // 0..127
            int kq  = fid & 3;                // which float4 of 16 k
            float4 vx = *(const float4*)(x + (size_t)(m0 + row) * 128 + kk + kq * 4);
            xs[kq * 4 + 0][row] = vx.x;
            xs[kq * 4 + 1][row] = vx.y;
            xs[kq * 4 + 2][row] = vx.z;
            xs[kq * 4 + 3][row] = vx.w;
        }
        // M tile: 16 k x 128 n -> ms[k][n] (direct)
        #pragma unroll
        for (int i = 0; i < 2; i++) {
            int fid = tid + i * 256;
            int k  = fid >> 5;                // 0..15
            int nq = fid & 31;                // 0..31 float4s per row
            *(float4*)&ms[k][nq * 4] = *(const float4*)(g_M + (kk + k) * 256 + n0 + nq * 4);
        }
        __syncthreads();
        #pragma unroll
        for (int k = 0; k < 16; k++) {
            float a[8], b[8];
            #pragma unroll
            for (int i = 0; i < 8; i++) a[i] = xs[k][ty * 8 + i];
            #pragma unroll
            for (int j = 0; j < 8; j++) b[j] = ms[k][tx * 8 + j];
            #pragma unroll
            for (int i = 0; i < 8; i++)
                #pragma unroll
                for (int j = 0; j < 8; j++) acc[i][j] += a[i] * b[j];
        }
        __syncthreads();
    }

    // epilogue: out = alpha * (acc + d) + c/8
    float dn[8], cn[8];
    #pragma unroll
    for (int j = 0; j < 8; j++) {
        int n = n0 + tx * 8 + j;
        dn[j] = g_d[n];
        cn[j] = g_c8[n];
    }
    #pragma unroll
    for (int i = 0; i < 8; i++) {
        int m = m0 + ty * 8 + i;
        float al = g_alpha[opt[m]];
        float4 o0, o1;
        o0.x = al * (acc[i][0] + dn[0]) + cn[0];
        o0.y = al * (acc[i][1] + dn[1]) + cn[1];
        o0.z = al * (acc[i][2] + dn[2]) + cn[2];
        o0.w = al * (acc[i][3] + dn[3]) + cn[3];
        o1.x = al * (acc[i][4] + dn[4]) + cn[4];
        o1.y = al * (acc[i][5] + dn[5]) + cn[5];
        o1.z = al * (acc[i][6] + dn[6]) + cn[6];
        o1.w = al * (acc[i][7] + dn[7]) + cn[7];
        float* po = out + (size_t)m * 256 + n0 + tx * 8;
        *(float4*)(po)     = o0;
        *(float4*)(po + 4) = o1;
    }
}

extern "C" void kernel_launch(void* const* d_in, const int* in_sizes, int n_in,
                              void* d_out, int out_size) {
    const float* x        = (const float*)d_in[0];   // (8192,128)
    const int*   option   = (const int*)  d_in[1];   // (8192,)
    const float* pre_fc_w = (const float*)d_in[2];   // (128,512)
    const float* pre_fc_b = (const float*)d_in[3];   // (512,)
    const float* value_w  = (const float*)d_in[4];   // (512,1024)
    const float* value_b  = (const float*)d_in[5];   // (1024,)
    const float* p_w      = (const float*)d_in[6];   // (16,64)
    const float* p_b      = (const float*)d_in[7];   // (64,)
    float* out = (float*)d_out;                      // (8192,256)

    prep_kernel<<<1, 256>>>(p_w, p_b, value_b);
    wprime_kernel<<<512, 256>>>(value_w);
    mgemm_kernel<<<dim3(33, 4), 256>>>(pre_fc_w, pre_fc_b);
    main_gemm<<<dim3(64, 2), 256>>>(x, option, out);
}

// round 4
// speedup vs baseline: 1.0069x; 1.0069x over previous
#include <cuda_runtime.h>
#include <cuda_bf16.h>
#include <stdint.h>
#include <string.h>
#include <math.h>

// ---------------- scratch (no allocations allowed) ----------------
__device__ __align__(16) float g_Md[129 * 256];   // rows 0..127: M = pre_fc_w @ mean_h(value_w); row 128: d
__device__ __align__(16) float g_c8[256];         // mean-over-heads value_b / 8
__device__ __align__(16) float g_alpha[16];       // per-option: sum_{top8} sigmoid(score) / 64

// packed fp32x2 helpers (Blackwell FFMA2; compute_103-legal, unlike tcgen05)
#define FMA2(d, a, b) asm("fma.rn.f32x2 %0, %1, %2, %0;" : "+l"(d) : "l"(a), "l"(b))
#define DUP2(d, f)    asm("mov.b64 %0, {%1, %1};" : "=l"(d) : "f"(f))

// ---------------- kernel 1: M/d GEMM (head-mean folded) + alpha/c8 LUT ----------------
// grid 129: blocks 0..127 = (n-tile 0..7) x (k-split 0..15); block 128 = LUT.
// M[o][v] = sum_k pre_fc_w[o][k] * 0.25*sum_h value_w[k][v + 256h]   (o=128 row uses pre_fc_b)
__global__ __launch_bounds__(256) void prep_all(const float* __restrict__ A,    // pre_fc_w (128,512)
                                                const float* __restrict__ bias, // pre_fc_b (512,)
                                                const float* __restrict__ vw,   // value_w (512,1024)
                                                const float* __restrict__ pw,   // p_w (16,64)
                                                const float* __restrict__ pb,   // p_b (64,)
                                                const float* __restrict__ vb) { // value_b (1024,)
    int b = blockIdx.x;
    int tid = threadIdx.x;

    if (b == 128) {
        // alpha LUT + c/8
        float c = 0.25f * (vb[tid] + vb[tid + 256] + vb[tid + 512] + vb[tid + 768]);
        g_c8[tid] = 0.125f * c;
        __shared__ float s[16][64];
        for (int i = tid; i < 16 * 64; i += 256) s[i >> 6][i & 63] = pw[i] + pb[i & 63];
        __syncthreads();
        if (tid < 16) {
            float S = 0.f;
            for (int j = 0; j < 8; j++) {
                float bv = -1e30f; int bi = 0;
                for (int n = 0; n < 64; n++) {
                    float val = s[tid][n];
                    if (val > bv) { bv = val; bi = n; }
                }
                S += 1.f / (1.f + expf(-bv));   // softmax([x,0])[0] = sigmoid(x)
                s[tid][bi] = -1e30f;
            }
            g_alpha[tid] = S * (1.0f / 64.0f);
        }
        return;
    }

    int nt = b & 7;          // n0 = nt*32
    int ks = b >> 3;         // k0 = ks*32
    int n0 = nt * 32, k0 = ks * 32;

    __shared__ float sA[129][33];                  // [row][k], padded (scalar access only)
    __shared__ __align__(16) float sB[32][32];     // [k][n], folded over heads (float4 reads)

    // load A chunk (129 rows x 32 k)
    for (int idx = tid; idx < 129 * 32; idx += 256) {
        int o = idx >> 5, k = idx & 31;
        sA[o][k] = (o < 128) ? A[o * 512 + k0 + k] : bias[k0 + k];
    }
    // load + fold B chunk (32 k x 32 n)
    #pragma unroll
    for (int i = 0; i < 4; i++) {
        int idx = tid + i * 256;
        int k = idx >> 5, n = idx & 31;
        const float* p = vw + (size_t)(k0 + k) * 1024 + n0 + n;
        sB[k][n] = 0.25f * (p[0] + p[256] + p[512] + p[768]);
    }
    __syncthreads();

    int tx = tid & 7;        // n quad
    int ty = tid >> 3;       // 0..31
    float acc[5][4] = {};
    #pragma unroll 4
    for (int k = 0; k < 32; k++) {
        float4 b4 = *(const float4*)&sB[k][tx * 4];
        #pragma unroll
        for (int rr = 0; rr < 4; rr++) {
            float a = sA[ty + rr * 32][k];
            acc[rr][0] += a * b4.x; acc[rr][1] += a * b4.y;
            acc[rr][2] += a * b4.z; acc[rr][3] += a * b4.w;
        }
        if (ty == 0) {
            float a = sA[128][k];
            acc[4][0] += a * b4.x; acc[4][1] += a * b4.y;
            acc[4][2] += a * b4.z; acc[4][3] += a * b4.w;
        }
    }
    #pragma unroll
    for (int rr = 0; rr < 4; rr++) {
        int o = ty + rr * 32;
        #pragma unroll
        for (int j = 0; j < 4; j++)
            atomicAdd(&g_Md[o * 256 + n0 + tx * 4 + j], acc[rr][j]);
    }
    if (ty == 0) {
        #pragma unroll
        for (int j = 0; j < 4; j++)
            atomicAdd(&g_Md[128 * 256 + n0 + tx * 4 + j], acc[4][j]);
    }
}

// ---------------- kernel 2: main GEMM with fp32x2 packed FMA ----------------
// out[m,n] = alpha[opt[m]] * ((x@M)[m,n] + d[n]) + c8[n]
// CTA tile 64m x 128n, K=128 in two chunks of 64. 256 threads, per-thread 4m x 8n
// (n packed as 4 f32x2 pairs -> only 4 a-dups per k). grid (128, 2).
static constexpr int XS_LD = 68;                      // row pad: keeps float4 align, kills conflicts
static constexpr int SMEM_MAIN = (64 * XS_LD + 64 * 128 + 64) * 4;

__global__ __launch_bounds__(256) void main_f2(const float* __restrict__ x,    // (8192,128)
                                               const int* __restrict__ opt,    // (8192,)
                                               float* __restrict__ out) {      // (8192,256)
    extern __shared__ __align__(16) float smf[];
    float* xs  = smf;                         // [64][XS_LD]  x tile, natural [m][k]
    float* ms  = smf + 64 * XS_LD;            // [64][128]    M tile, [k][n]
    float* als = smf + 64 * XS_LD + 64 * 128; // [64] per-row alpha

    int tid = threadIdx.x;
    int m0 = blockIdx.x * 64;
    int n0 = blockIdx.y * 128;
    int tx = tid & 15;       // n = tx*8
    int ty = tid >> 4;       // m = ty*4

    if (tid < 64) als[tid] = g_alpha[opt[m0 + tid]];

    // per-thread column constants
    int nc = n0 + tx * 8;
    float4 dd0 = *(const float4*)&g_Md[128 * 256 + nc];
    float4 dd1 = *(const float4*)&g_Md[128 * 256 + nc + 4];
    float4 cc0 = *(const float4*)&g_c8[nc];
    float4 cc1 = *(const float4*)&g_c8[nc + 4];

    unsigned long long acc[4][4];
    #pragma unroll
    for (int i = 0; i < 4; i++)
        #pragma unroll
        for (int p = 0; p < 4; p++) acc[i][p] = 0ull;

    for (int c = 0; c < 2; c++) {
        int kc = c * 64;
        if (c) __syncthreads();
        // x tile: 64 rows x 64 k (coalesced float4 along k)
        #pragma unroll
        for (int i = 0; i < 4; i++) {
            int id = tid + i * 256;         // 0..1023
            int m = id >> 4, kq = id & 15;
            float4 v = *(const float4*)(x + (size_t)(m0 + m) * 128 + kc + kq * 4);
            *(float4*)(xs + m * XS_LD + kq * 4) = v;
        }
        // M tile: 64 k x 128 n (direct float4)
        #pragma unroll
        for (int i = 0; i < 8; i++) {
            int id = tid + i * 256;         // 0..2047
            int k = id >> 5, n4 = id & 31;
            *(float4*)(ms + k * 128 + n4 * 4) =
                *(const float4*)(g_Md + (size_t)(kc + k) * 256 + n0 + n4 * 4);
        }
        __syncthreads();

        #pragma unroll 4
        for (int k = 0; k < 64; k++) {
            const ulonglong2* bp = (const ulonglong2*)(ms + k * 128 + tx * 8);
            ulonglong2 b01 = bp[0];
            ulonglong2 b23 = bp[1];
            unsigned long long ad[4];
            #pragma unroll
            for (int i = 0; i < 4; i++) {
                float a = xs[(ty * 4 + i) * XS_LD + k];
                DUP2(ad[i], a);
            }
            #pragma unroll
            for (int i = 0; i < 4; i++) {
                FMA2(acc[i][0], ad[i], b01.x);
                FMA2(acc[i][1], ad[i], b01.y);
                FMA2(acc[i][2], ad[i], b23.x);
                FMA2(acc[i][3], ad[i], b23.y);
            }
        }
    }

    // epilogue
    #pragma unroll
    for (int i = 0; i < 4; i++) {
        int ml = ty * 4 + i;
        float al = als[ml];
        float2 f[4];
        #pragma unroll
        for (int p = 0; p < 4; p++) memcpy(&f[p], &acc[i][p], 8);
        float4 o0, o1;
        o0.x = fmaf(f[0].x, al, fmaf(dd0.x, al, cc0.x));
        o0.y = fmaf(f[0].y, al, fmaf(dd0.y, al, cc0.y));
        o0.z = fmaf(f[1].x, al, fmaf(dd0.z, al, cc0.z));
        o0.w = fmaf(f[1].y, al, fmaf(dd0.w, al, cc0.w));
        o1.x = fmaf(f[2].x, al, fmaf(dd1.x, al, cc1.x));
        o1.y = fmaf(f[2].y, al, fmaf(dd1.y, al, cc1.y));
        o1.z = fmaf(f[3].x, al, fmaf(dd1.z, al, cc1.z));
        o1.w = fmaf(f[3].y, al, fmaf(dd1.w, al, cc1.w));
        float* po = out + (size_t)(m0 + ml) * 256 + nc;
        *(float4*)(po)     = o0;
        *(float4*)(po + 4) = o1;
    }
}

extern "C" void kernel_launch(void* const* d_in, const int* in_sizes, int n_in,
                              void* d_out, int out_size) {
    const float* x        = (const float*)d_in[0];   // (8192,128)
    const int*   option   = (const int*)  d_in[1];   // (8192,)
    const float* pre_fc_w = (const float*)d_in[2];   // (128,512)
    const float* pre_fc_b = (const float*)d_in[3];   // (512,)
    const float* value_w  = (const float*)d_in[4];   // (512,1024)
    const float* value_b  = (const float*)d_in[5];   // (1024,)
    const float* p_w      = (const float*)d_in[6];   // (16,64)
    const float* p_b      = (const float*)d_in[7];   // (64,)
    float* out = (float*)d_out;                      // (8192,256)

    void* pMd = nullptr;
    cudaGetSymbolAddress(&pMd, g_Md);
    cudaMemsetAsync(pMd, 0, 129 * 256 * sizeof(float));

    cudaFuncSetAttribute(main_f2, cudaFuncAttributeMaxDynamicSharedMemorySize, SMEM_MAIN);

    prep_all<<<129, 256>>>(pre_fc_w, pre_fc_b, value_w, p_w, p_b, value_b);
    main_f2<<<dim3(128, 2), 256, SMEM_MAIN>>>(x, option, out);
}